// round 7
// baseline (speedup 1.0000x reference)
#include <cuda_runtime.h>
#include <cuda_fp16.h>
#include <mma.h>
using namespace nvcuda;

#define B_    256
#define TIN   512
#define TOUT  256
#define NSTEP 255
#define RING_D 8

// ---------- device scratch ----------
__device__ __half g_mem16[(size_t)B_*TIN*256];
__device__ __half g_keys [(size_t)B_*TIN*256];  // memory @ Wm
__device__ __half g_mema [(size_t)B_*TIN*256];  // memory @ Wa[256:512]
__device__ __half g_W2t[512*1024];  // idx = kb*8192 + np*8 + kk ; np=u*4+g ; k=kb*8+kk
__device__ __half g_Wqt[256*512];   // idx = kb*4096 + n*8 + kk  ; n<256:Wq, else Wa1
__device__ float  g_zbp[6*1024];    // Wi[v]+b, np-permuted
__device__ __half g_Wm16[256*256];
__device__ __half g_Wa2 [256*256];

__device__ __forceinline__ float sigf(float x){ return 1.f/(1.f+expf(-x)); }
__device__ __forceinline__ float tanh_fast(float x){
  float y; asm("tanh.approx.f32 %0, %1;" : "=f"(y) : "f"(x)); return y;
}

// ---------- prologue ----------
__global__ void prep_small(const float* __restrict__ Wi, const float* __restrict__ Wh,
                           const float* __restrict__ bias, const float* __restrict__ Wm,
                           const float* __restrict__ Wq, const float* __restrict__ Wa){
  int i = blockIdx.x*256 + threadIdx.x;        // 0..524287
  { // W2t
    int kb = i>>13, rem = i&8191, np = rem>>3, kk = rem&7;
    int k = kb*8+kk, u = np>>2, g = np&3, n = g*256+u;
    float w = (k<256) ? Wi[(6+k)*1024+n] : Wh[(k-256)*1024+n];
    g_W2t[i] = __float2half(w); }
  if (i < 6*1024){
    int vv = i>>10, np = i&1023, u = np>>2, g = np&3, n = g*256+u;
    g_zbp[i] = Wi[vv*1024+n] + bias[n]; }
  if (i < 131072){
    int kb = i>>12, rem = i&4095, n = rem>>3, kk = rem&7;
    int k = kb*8+kk;
    g_Wqt[i] = __float2half(n<256 ? Wq[k*256+n] : Wa[k*256+(n-256)]); }
  if (i < 65536){
    g_Wm16[i] = __float2half(Wm[i]);
    g_Wa2[i]  = __float2half(Wa[65536+i]); }
}

__global__ void prep_big(const float4* __restrict__ mem){
  int i = blockIdx.x*256 + threadIdx.x;
  float4 f = mem[i];
  __half2* o = reinterpret_cast<__half2*>(g_mem16) + (size_t)i*2;
  o[0] = __floats2half2_rn(f.x,f.y);
  o[1] = __floats2half2_rn(f.z,f.w);
}

// keys/mema = g_mem16 @ (Wm16 | Wa2), smem-staged (from R6, passing)
#define GA_LD 264
#define GB_LD 80
__global__ void gemm_keys2(){
  extern __shared__ char smc[];
  __half* As = (__half*)smc;
  __half* Bs = (__half*)(smc + 64*GA_LD*2);
  float*  epi = (float*)smc;
  int which = blockIdx.z;
  const __half* Bm = which ? g_Wa2 : g_Wm16;
  __half* C        = which ? g_mema : g_keys;
  size_t m0 = (size_t)blockIdx.y*64;
  int n0 = blockIdx.x*64;
  int tid = threadIdx.x;
  #pragma unroll
  for (int j=0;j<8;j++){
    int idx = tid + j*256, r = idx>>5, c = idx&31;
    *(uint4*)(As + r*GA_LD + c*8) = *(const uint4*)(g_mem16 + (m0+r)*256 + c*8);
  }
  #pragma unroll
  for (int j=0;j<8;j++){
    int idx = tid + j*256, r = idx>>3, c = idx&7;
    *(uint4*)(Bs + r*GB_LD + c*8) = *(const uint4*)(Bm + r*256 + n0 + c*8);
  }
  __syncthreads();
  int w = tid>>5, wm = w>>1, wn = w&1;
  wmma::fragment<wmma::accumulator,16,16,16,float> a0,a1;
  wmma::fill_fragment(a0,0.f); wmma::fill_fragment(a1,0.f);
  #pragma unroll
  for (int k=0;k<256;k+=16){
    wmma::fragment<wmma::matrix_a,16,16,16,__half,wmma::row_major> a;
    wmma::load_matrix_sync(a, As + (wm*16)*GA_LD + k, GA_LD);
    wmma::fragment<wmma::matrix_b,16,16,16,__half,wmma::row_major> b0,b1;
    wmma::load_matrix_sync(b0, Bs + k*GB_LD + wn*32,    GB_LD);
    wmma::load_matrix_sync(b1, Bs + k*GB_LD + wn*32+16, GB_LD);
    wmma::mma_sync(a0,a,b0,a0); wmma::mma_sync(a1,a,b1,a1);
  }
  __syncthreads();
  wmma::store_matrix_sync(epi + (wm*16)*72 + wn*32,    a0, 72, wmma::mem_row_major);
  wmma::store_matrix_sync(epi + (wm*16)*72 + wn*32+16, a1, 72, wmma::mem_row_major);
  __syncthreads();
  #pragma unroll
  for (int j=0;j<16;j++){
    int idx = tid + j*256, r = idx>>6, c = idx&63;
    C[(m0+r)*256 + n0 + c] = __float2half(epi[r*72 + c]);
  }
}

// ---------- persistent decoder: 128 blocks x 512 thr; 2 groups of 256 (1 batch each) ----------
#define GBAR(g) asm volatile("bar.sync %0, 256;" :: "r"((g)+1) : "memory")

__device__ __forceinline__ float dot8(uint4 wv, const float* a){
  const __half2* h = (const __half2*)&wv;
  float acc = 0.f;
  #pragma unroll
  for (int p=0;p<4;p++){
    float2 f = __half22float2(h[p]);
    acc = fmaf(f.x, a[2*p], acc);
    acc = fmaf(f.y, a[2*p+1], acc);
  }
  return acc;
}

__global__ __launch_bounds__(512,1) void decoder_persist(
    const int* __restrict__ ids, const float* __restrict__ enc_h,
    const float* __restrict__ enc_c, const float* __restrict__ v,
    const float* __restrict__ Wf, const float* __restrict__ bf,
    float* __restrict__ out)
{
  extern __shared__ char sm[];
  __half* ring = (__half*)sm;                   // 16 warps x 8 slots x 1KB = 128KB
  float* F     = (float*)(sm + 131072);
  float* s_zbp = F;            // 6144
  float* s_ctx = F + 6144;     // [2][8][256]
  float* s_act = F + 10240;    // [2][512]  attn|h  (fp32)
  float* s_c   = F + 11264;    // [2][256]
  float* s_pqb = F + 11776;    // [2][512]  pq|base
  float* s_v   = F + 12800;    // 256
  float* s_Wf  = F + 13056;    // 1536
  float* s_bf  = F + 14592;    // 6 (+pad)
  float* s_d   = F + 14600;    // [2][8]
  int*   s_id  = (int*)(F + 14616);

  int tid = threadIdx.x;
  int grp = tid >> 8;
  int gt  = tid & 255;
  int bg  = blockIdx.x*2 + grp;
  int w   = tid >> 5;
  int gw  = gt >> 5;
  int lane = tid & 31;

  for (int i = tid; i < 6144; i += 512) s_zbp[i] = g_zbp[i];
  for (int i = tid; i < 1536; i += 512) s_Wf[i] = Wf[i];
  if (tid < 256) s_v[tid] = v[tid];
  if (tid < 6)  s_bf[tid] = bf[tid];
  s_act[grp*512 + gt]       = 0.f;
  s_act[grp*512 + 256 + gt] = enc_h[bg*256 + gt];
  s_c[grp*256 + gt]         = enc_c[bg*256 + gt];
  __syncthreads();

  const __half* keysB = g_keys + (size_t)bg*TIN*256;
  const __half* maB   = g_mema + (size_t)bg*TIN*256;
  int u0 = lane*8;
  unsigned rbase = (unsigned)__cvta_generic_to_shared(ring) + (unsigned)(w*RING_D*1024);

#define ISSUE(i_) { int t_ = gw + (i_)*8; unsigned d_ = rbase + ((i_)&7)*1024 + lane*16;        \
    asm volatile("cp.async.cg.shared.global [%0], [%1], 16;\n"                                  \
                 "cp.async.cg.shared.global [%2], [%3], 16;\n"                                  \
                 "cp.async.commit_group;\n"                                                     \
      :: "r"(d_), "l"(keysB + (size_t)t_*256 + u0), "r"(d_+512), "l"(maB + (size_t)t_*256 + u0)); }

  #pragma unroll 1
  for (int s = 0; s < NSTEP; s++){
    if (gt == 0) s_id[grp] = ids[bg*TOUT + s];
    // kick attention prefetch early (overlaps GEMVs)
    #pragma unroll
    for (int i=0;i<7;i++) ISSUE(i);

    // ---- Phase L: z[u, 4 gates] GEMV, thread gt owns u=gt (np 4gt..4gt+3)
    float z0=0,z1=0,z2=0,z3=0;
    { const float* A = s_act + grp*512;
      #pragma unroll 2
      for (int kb=0; kb<64; kb++){
        const __half* wp = g_W2t + kb*8192 + gt*32;
        uint4 w0 = *(const uint4*)(wp);
        uint4 w1 = *(const uint4*)(wp+8);
        uint4 w2 = *(const uint4*)(wp+16);
        uint4 w3 = *(const uint4*)(wp+24);
        float a[8];
        *(float4*)a     = *(const float4*)(A + kb*8);
        *(float4*)(a+4) = *(const float4*)(A + kb*8 + 4);
        z0 += dot8(w0,a); z1 += dot8(w1,a); z2 += dot8(w2,a); z3 += dot8(w3,a);
      } }
    GBAR(grp);   // s_id visible
    { int id = s_id[grp];
      float4 zb = *(const float4*)(s_zbp + id*1024 + gt*4);
      z0 += zb.x; z1 += zb.y; z2 += zb.z; z3 += zb.w;
      float c  = s_c[grp*256+gt];
      float cn = sigf(z1)*c + sigf(z0)*tanhf(z2);
      float hn = sigf(z3)*tanhf(cn);
      s_c[grp*256+gt] = cn;
      s_act[grp*512+256+gt] = hn; }
    GBAR(grp);   // h complete

    // ---- Phase Q: [pq|base] = h @ [Wq|Wa1], thread gt owns cols 2gt,2gt+1
    { const float* H = s_act + grp*512 + 256;
      float q0=0,q1=0;
      #pragma unroll 2
      for (int kb=0; kb<32; kb++){
        const __half* wp = g_Wqt + kb*4096 + gt*16;
        uint4 w0 = *(const uint4*)(wp);
        uint4 w1 = *(const uint4*)(wp+8);
        float a[8];
        *(float4*)a     = *(const float4*)(H + kb*8);
        *(float4*)(a+4) = *(const float4*)(H + kb*8 + 4);
        q0 += dot8(w0,a); q1 += dot8(w1,a);
      }
      s_pqb[grp*512 + 2*gt]   = q0;
      s_pqb[grp*512 + 2*gt+1] = q1; }
    GBAR(grp);   // pq ready

    // ---- Phase A: flash attention, no-max softmax (scores bounded)
    { float pqr[8], vr[8];
      #pragma unroll
      for (int k=0;k<8;k++){ pqr[k] = s_pqb[grp*512 + u0+k]; vr[k] = s_v[u0+k]; }
      float d = 0.f, C[8];
      #pragma unroll
      for (int k=0;k<8;k++) C[k]=0.f;
      const char* rg = (const char*)ring + w*RING_D*1024;
      #pragma unroll 2
      for (int i=0;i<64;i++){
        if (i < 57)       asm volatile("cp.async.wait_group 6;" ::: "memory");
        else if (i == 57) asm volatile("cp.async.wait_group 0;" ::: "memory");
        uint4 kv = *(const uint4*)(rg + ((i)&7)*1024 + lane*16);
        uint4 mv = *(const uint4*)(rg + ((i)&7)*1024 + 512 + lane*16);
        if (i+7 < 64) ISSUE(i+7);
        const __half2* kh = (const __half2*)&kv;
        const __half2* mh = (const __half2*)&mv;
        float mf[8]; float sc = 0.f;
        #pragma unroll
        for (int p=0;p<4;p++){
          float2 kf = __half22float2(kh[p]);
          float2 vf = __half22float2(mh[p]);
          mf[2*p] = vf.x; mf[2*p+1] = vf.y;
          sc += vr[2*p]   * tanh_fast(kf.x + pqr[2*p]);
          sc += vr[2*p+1] * tanh_fast(kf.y + pqr[2*p+1]);
        }
        #pragma unroll
        for (int o=16;o;o>>=1) sc += __shfl_xor_sync(0xffffffffu, sc, o);
        float p_ = __expf(sc);
        d += p_;
        #pragma unroll
        for (int k=0;k<8;k++) C[k] = fmaf(p_, mf[k], C[k]);
      }
      if (lane==0) s_d[grp*8+gw] = d;
      #pragma unroll
      for (int k=0;k<8;k++) s_ctx[(grp*8+gw)*256 + u0+k] = C[k];
      GBAR(grp);
      { float D = 0.f, ctx = 0.f;
        #pragma unroll
        for (int k=0;k<8;k++){ D += s_d[grp*8+k]; ctx += s_ctx[(grp*8+k)*256 + gt]; }
        float attn = s_pqb[grp*512+256+gt] + ctx/D;
        s_act[grp*512+gt] = attn; }
      GBAR(grp);
      if (gw < 6){
        float acc = 0.f;
        #pragma unroll
        for (int u=lane; u<256; u+=32) acc += s_act[grp*512+u]*s_Wf[u*6+gw];
        #pragma unroll
        for (int o=16;o;o>>=1) acc += __shfl_xor_sync(0xffffffffu, acc, o);
        if (lane==0) out[((size_t)bg*NSTEP + s)*6 + gw] = acc + s_bf[gw];
      }
    }
  }
#undef ISSUE
}

extern "C" void kernel_launch(void* const* d_in, const int* in_sizes, int n_in,
                              void* d_out, int out_size){
  const int*   ids    = (const int*)  d_in[0];
  const float* memory = (const float*)d_in[1];
  const float* enc_h  = (const float*)d_in[2];
  const float* enc_c  = (const float*)d_in[3];
  const float* Wi     = (const float*)d_in[4];
  const float* Wh     = (const float*)d_in[5];
  const float* b      = (const float*)d_in[6];
  const float* Wm     = (const float*)d_in[7];
  const float* Wq     = (const float*)d_in[8];
  const float* v      = (const float*)d_in[9];
  const float* Wa     = (const float*)d_in[10];
  const float* Wf     = (const float*)d_in[11];
  const float* bf     = (const float*)d_in[12];
  float* out = (float*)d_out;

  const int gk_smem = 64*GA_LD*2 + 256*GB_LD*2;
  const int dp_smem = 131072 + 14720*4;           // ~190 KB
  cudaFuncSetAttribute(gemm_keys2, cudaFuncAttributeMaxDynamicSharedMemorySize, gk_smem);
  cudaFuncSetAttribute(decoder_persist, cudaFuncAttributeMaxDynamicSharedMemorySize, dp_smem);

  prep_small<<<2048,256>>>(Wi,Wh,b,Wm,Wq,Wa);
  prep_big<<<32768,256>>>((const float4*)memory);
  gemm_keys2<<<dim3(4,2048,2),256,gk_smem>>>();
  decoder_persist<<<128,512,dp_smem>>>(ids, enc_h, enc_c, v, Wf, bf, out);
}

// round 11
// speedup vs baseline: 2.1475x; 2.1475x over previous
#include <cuda_runtime.h>
#include <cuda_fp16.h>
#include <mma.h>
using namespace nvcuda;

#define B_    256
#define TIN   512
#define TOUT  256
#define NSTEP 255

// ---------- device scratch ----------
__device__ __half g_mem16[(size_t)B_*TIN*256];
__device__ __half g_keys [(size_t)B_*TIN*256];  // memory @ Wm
__device__ __half g_mema [(size_t)B_*TIN*256];  // memory @ Wa[256:512]
__device__ __half g_W2p[512*1024];              // [Wi[6:]; Wh], cols permuted np=u*4+g
__device__ __half g_Wqt[256*512];               // kb*4096 + n*8 + kk ; n<256:Wq else Wa1
__device__ float  g_zbp[6*1024];                // Wi[v]+b, np-permuted
__device__ __half g_Wm16[256*256];
__device__ __half g_Wa2 [256*256];
__device__ __half g_act[2*B_*512];              // [attn(256)|h(256)] double-buffered
__device__ float  g_c[B_*256];                  // cell state fp32

__device__ __forceinline__ float sigf(float x){ return 1.f/(1.f+expf(-x)); }
__device__ __forceinline__ float tanh_fast(float x){
  float y; asm("tanh.approx.f32 %0, %1;" : "=f"(y) : "f"(x)); return y;
}
__device__ __forceinline__ float dot8(uint4 wv, const float* a){
  const __half2* h = (const __half2*)&wv;
  float acc = 0.f;
  #pragma unroll
  for (int p=0;p<4;p++){
    float2 f = __half22float2(h[p]);
    acc = fmaf(f.x, a[2*p], acc);
    acc = fmaf(f.y, a[2*p+1], acc);
  }
  return acc;
}

// ---------- prologue ----------
__global__ void prep_small(const float* __restrict__ Wi, const float* __restrict__ Wh,
                           const float* __restrict__ bias, const float* __restrict__ Wm,
                           const float* __restrict__ Wq, const float* __restrict__ Wa,
                           const float* __restrict__ enc_h, const float* __restrict__ enc_c){
  int i = blockIdx.x*256 + threadIdx.x;        // 0..524287
  { int k = i>>10, np = i&1023, u = np>>2, g = np&3, n = g*256+u;
    float w = (k<256) ? Wi[(6+k)*1024+n] : Wh[(k-256)*1024+n];
    g_W2p[i] = __float2half(w); }
  if (i < 6*1024){
    int vv = i>>10, np = i&1023, u = np>>2, g = np&3, n = g*256+u;
    g_zbp[i] = Wi[vv*1024+n] + bias[n]; }
  if (i < 131072){
    int kb = i>>12, rem = i&4095, n = rem>>3, kk = rem&7;
    int k = kb*8+kk;
    g_Wqt[i] = __float2half(n<256 ? Wq[k*256+n] : Wa[k*256+(n-256)]); }
  if (i < 65536){
    g_Wm16[i] = __float2half(Wm[i]);
    g_Wa2[i]  = __float2half(Wa[65536+i]);
    g_c[i] = enc_c[i];
    int bb = i>>8, uu = i&255;
    g_act[bb*512+uu]     = __float2half(0.f);
    g_act[bb*512+256+uu] = __float2half(enc_h[i]); }
}

__global__ void prep_big(const float4* __restrict__ mem){
  int i = blockIdx.x*256 + threadIdx.x;
  float4 f = mem[i];
  __half2* o = reinterpret_cast<__half2*>(g_mem16) + (size_t)i*2;
  o[0] = __floats2half2_rn(f.x,f.y);
  o[1] = __floats2half2_rn(f.z,f.w);
}

// keys & mema in one pass: A tile loaded once, loop over both B matrices.
#define GA_LD 264
#define GB_LD 80
__global__ void gemm_keys2(){
  extern __shared__ char smc[];
  __half* As = (__half*)smc;                       // 64 x GA_LD
  __half* Bs = (__half*)(smc + 64*GA_LD*2);        // 256 x GB_LD
  float*  epi = (float*)(smc + 64*GA_LD*2);        // overlay on Bs after k-loop
  size_t m0 = (size_t)blockIdx.y*64;
  int n0 = blockIdx.x*64;
  int tid = threadIdx.x;
  #pragma unroll
  for (int j=0;j<8;j++){
    int idx = tid + j*256, r = idx>>5, c = idx&31;
    *(uint4*)(As + r*GA_LD + c*8) = *(const uint4*)(g_mem16 + (m0+r)*256 + c*8);
  }
  int w = tid>>5, wm = w>>1, wn = w&1;
  #pragma unroll
  for (int which=0; which<2; which++){
    const __half* Bm = which ? g_Wa2 : g_Wm16;
    __half* C        = which ? g_mema : g_keys;
    #pragma unroll
    for (int j=0;j<8;j++){
      int idx = tid + j*256, r = idx>>3, c = idx&7;
      *(uint4*)(Bs + r*GB_LD + c*8) = *(const uint4*)(Bm + r*256 + n0 + c*8);
    }
    __syncthreads();
    wmma::fragment<wmma::accumulator,16,16,16,float> a0,a1;
    wmma::fill_fragment(a0,0.f); wmma::fill_fragment(a1,0.f);
    #pragma unroll
    for (int k=0;k<256;k+=16){
      wmma::fragment<wmma::matrix_a,16,16,16,__half,wmma::row_major> a;
      wmma::load_matrix_sync(a, As + (wm*16)*GA_LD + k, GA_LD);
      wmma::fragment<wmma::matrix_b,16,16,16,__half,wmma::row_major> b0,b1;
      wmma::load_matrix_sync(b0, Bs + k*GB_LD + wn*32,    GB_LD);
      wmma::load_matrix_sync(b1, Bs + k*GB_LD + wn*32+16, GB_LD);
      wmma::mma_sync(a0,a,b0,a0); wmma::mma_sync(a1,a,b1,a1);
    }
    __syncthreads();
    wmma::store_matrix_sync(epi + (wm*16)*72 + wn*32,    a0, 72, wmma::mem_row_major);
    wmma::store_matrix_sync(epi + (wm*16)*72 + wn*32+16, a1, 72, wmma::mem_row_major);
    __syncthreads();
    #pragma unroll
    for (int j=0;j<16;j++){
      int idx = tid + j*256, r = idx>>6, c = idx&63;
      C[(m0+r)*256 + n0 + c] = __float2half(epi[r*72 + c]);
    }
    __syncthreads();
  }
}

// ---------- LSTM step (R6, proven): grid (16, 8), 256 thr ----------
#define LA_LD 520
#define LB_LD 80
__global__ void lstm_step(const int* __restrict__ ids, int step){
  extern __shared__ char smc[];
  __half* As = (__half*)smc;
  __half* Bs = (__half*)(smc + 32*LA_LD*2);
  float*  epi = (float*)(smc + 32*LA_LD*2);
  int pr = step&1;
  const __half* actR = g_act + pr*(B_*512);
  __half*       actW = g_act + (pr^1)*(B_*512);
  int tid = threadIdx.x;
  int n0g = blockIdx.x*64, b0 = blockIdx.y*32;
  #pragma unroll
  for (int j=0;j<8;j++){
    int idx = tid + j*256, r = idx>>6, c = idx&63;
    *(uint4*)(As + r*LA_LD + c*8) = *(const uint4*)(actR + (b0+r)*512 + c*8);
  }
  #pragma unroll
  for (int j=0;j<2;j++){
    int idx = tid + j*256, r = idx>>3, c = idx&7;
    *(uint4*)(Bs + r*LB_LD + c*8) = *(const uint4*)(g_W2p + r*1024 + n0g + c*8);
  }
  __syncthreads();
  int w = tid>>5, wm = w>>2, wn = w&3;
  wmma::fragment<wmma::accumulator,16,16,16,float> acc;
  wmma::fill_fragment(acc, 0.f);
  #pragma unroll
  for (int kc=0; kc<8; kc++){
    int cur = kc&1;
    if (kc < 7){
      int nxt = cur^1;
      #pragma unroll
      for (int j=0;j<2;j++){
        int idx = tid + j*256, r = idx>>3, c = idx&7;
        *(uint4*)(Bs + nxt*64*LB_LD + r*LB_LD + c*8) =
          *(const uint4*)(g_W2p + ((kc+1)*64 + r)*1024 + n0g + c*8);
      }
    }
    #pragma unroll
    for (int kk=0; kk<4; kk++){
      wmma::fragment<wmma::matrix_a,16,16,16,__half,wmma::row_major> a;
      wmma::load_matrix_sync(a, As + (wm*16)*LA_LD + kc*64 + kk*16, LA_LD);
      wmma::fragment<wmma::matrix_b,16,16,16,__half,wmma::row_major> b;
      wmma::load_matrix_sync(b, Bs + cur*64*LB_LD + (kk*16)*LB_LD + wn*16, LB_LD);
      wmma::mma_sync(acc, a, b, acc);
    }
    __syncthreads();
  }
  wmma::store_matrix_sync(epi + (wm*16)*72 + wn*16, acc, 72, wmma::mem_row_major);
  __syncthreads();
  #pragma unroll
  for (int j=0;j<2;j++){
    int idx = tid + j*256;
    int bl = idx>>4, ul = idx&15;
    int bg = b0+bl, ug = (n0g>>2)+ul;
    int id = ids[bg*TOUT + step];
    const float* zb = g_zbp + id*1024 + n0g + ul*4;
    float zi = epi[bl*72+ul*4+0]+zb[0];
    float zf = epi[bl*72+ul*4+1]+zb[1];
    float zg = epi[bl*72+ul*4+2]+zb[2];
    float zo = epi[bl*72+ul*4+3]+zb[3];
    float c  = g_c[bg*256+ug];
    float cn = sigf(zf)*c + sigf(zi)*tanhf(zg);
    float hn = sigf(zo)*tanhf(cn);
    g_c[bg*256+ug] = cn;
    actW[bg*512+256+ug] = __float2half(hn);
  }
}

// ---------- attention step: 256 blocks x 256 thr, cp.async ring depth 3 ----------
__global__ __launch_bounds__(256) void att_step(
    float* __restrict__ out, const float* __restrict__ v,
    const float* __restrict__ Wf, const float* __restrict__ bf, int step){
  int b = blockIdx.x;
  int pr = (step&1)^1;
  __half* act = g_act + pr*(B_*512) + b*512;
  extern __shared__ char sm[];
  __half* ring = (__half*)sm;                    // 8 warps x 4 slots x 1KB = 32KB
  float* F     = (float*)(sm + 32768);
  float* s_h    = F;
  float* s_pq   = F+256;
  float* s_base = F+512;
  float* s_v    = F+768;
  float* s_attn = F+1024;
  float* s_ctx  = F+1280;    // [8][256]
  float* s_d    = F+3328;    // 8
  int tid = threadIdx.x, lane = tid&31, w = tid>>5;
  int u0 = lane*8;
  const __half* keysB = g_keys + (size_t)b*TIN*256;
  const __half* maB   = g_mema + (size_t)b*TIN*256;
  unsigned rbase = (unsigned)__cvta_generic_to_shared(ring) + (unsigned)(w*4096);

#define AISSUE(i_) { int t_ = w*64 + (i_); unsigned d_ = rbase + ((i_)&3)*1024 + lane*16;     \
    asm volatile("cp.async.cg.shared.global [%0], [%1], 16;\n"                                \
                 "cp.async.cg.shared.global [%2], [%3], 16;\n"                                \
                 "cp.async.commit_group;\n"                                                   \
      :: "r"(d_), "l"(keysB + (size_t)t_*256 + u0), "r"(d_+512), "l"(maB + (size_t)t_*256 + u0)); }

  AISSUE(0); AISSUE(1); AISSUE(2);
  s_h[tid] = __half2float(act[256+tid]);
  s_v[tid] = v[tid];
  __syncthreads();
  // query GEMV: thread tid computes cols 2tid, 2tid+1 of [pq|base]
  { float q0=0.f, q1=0.f;
    #pragma unroll 4
    for (int kb=0; kb<32; kb++){
      const __half* wp = g_Wqt + kb*4096 + tid*16;
      uint4 w0 = *(const uint4*)(wp);
      uint4 w1 = *(const uint4*)(wp+8);
      float a[8];
      *(float4*)a     = *(const float4*)(s_h + kb*8);
      *(float4*)(a+4) = *(const float4*)(s_h + kb*8 + 4);
      q0 += dot8(w0,a); q1 += dot8(w1,a);
    }
    if (tid < 128){ s_pq[2*tid] = q0; s_pq[2*tid+1] = q1; }
    else { s_base[2*tid-256] = q0; s_base[2*tid-255] = q1; } }
  __syncthreads();

  float pqr[8], vr[8];
  #pragma unroll
  for (int k=0;k<8;k++){ pqr[k] = s_pq[u0+k]; vr[k] = s_v[u0+k]; }
  float d = 0.f, C[8];
  #pragma unroll
  for (int k=0;k<8;k++) C[k]=0.f;
  const char* rg = (const char*)ring + w*4096;
  #pragma unroll 4
  for (int i=0;i<64;i++){
    if (i < 61) asm volatile("cp.async.wait_group 2;" ::: "memory");
    else        asm volatile("cp.async.wait_group 0;" ::: "memory");
    uint4 kv = *(const uint4*)(rg + (i&3)*1024 + lane*16);
    uint4 mv = *(const uint4*)(rg + (i&3)*1024 + 512 + lane*16);
    if (i+3 < 64) AISSUE(i+3);
    const __half2* kh = (const __half2*)&kv;
    const __half2* mh = (const __half2*)&mv;
    float mf[8]; float sc = 0.f;
    #pragma unroll
    for (int p=0;p<4;p++){
      float2 kf = __half22float2(kh[p]);
      float2 vf = __half22float2(mh[p]);
      mf[2*p] = vf.x; mf[2*p+1] = vf.y;
      sc += vr[2*p]   * tanh_fast(kf.x + pqr[2*p]);
      sc += vr[2*p+1] * tanh_fast(kf.y + pqr[2*p+1]);
    }
    #pragma unroll
    for (int o=16;o;o>>=1) sc += __shfl_xor_sync(0xffffffffu, sc, o);
    float p_ = __expf(sc);
    d += p_;
    #pragma unroll
    for (int k=0;k<8;k++) C[k] = fmaf(p_, mf[k], C[k]);
  }
#undef AISSUE
  if (lane==0) s_d[w] = d;
  #pragma unroll
  for (int k=0;k<8;k++) s_ctx[w*256 + u0+k] = C[k];
  __syncthreads();
  { float D = 0.f, ctx = 0.f;
    #pragma unroll
    for (int k=0;k<8;k++){ D += s_d[k]; ctx += s_ctx[k*256 + tid]; }
    float attn = s_base[tid] + ctx/D;
    s_attn[tid] = attn;
    act[tid] = __float2half(attn); }
  __syncthreads();
  if (w < 6){
    float acc = 0.f;
    #pragma unroll
    for (int u=lane; u<256; u+=32) acc += s_attn[u]*Wf[u*6+w];
    #pragma unroll
    for (int o=16;o;o>>=1) acc += __shfl_xor_sync(0xffffffffu, acc, o);
    if (lane==0) out[((size_t)b*NSTEP + step)*6 + w] = acc + bf[w];
  }
}

extern "C" void kernel_launch(void* const* d_in, const int* in_sizes, int n_in,
                              void* d_out, int out_size){
  const int*   ids    = (const int*)  d_in[0];
  const float* memory = (const float*)d_in[1];
  const float* enc_h  = (const float*)d_in[2];
  const float* enc_c  = (const float*)d_in[3];
  const float* Wi     = (const float*)d_in[4];
  const float* Wh     = (const float*)d_in[5];
  const float* b      = (const float*)d_in[6];
  const float* Wm     = (const float*)d_in[7];
  const float* Wq     = (const float*)d_in[8];
  const float* v      = (const float*)d_in[9];
  const float* Wa     = (const float*)d_in[10];
  const float* Wf     = (const float*)d_in[11];
  const float* bf     = (const float*)d_in[12];
  float* out = (float*)d_out;

  const int gk_smem = 64*GA_LD*2 + 256*GB_LD*2;   // ~74 KB
  const int ls_smem = 32*LA_LD*2 + 2*64*LB_LD*2;  // ~54 KB
  const int at_smem = 32768 + 3336*4;             // ~46 KB
  cudaFuncSetAttribute(gemm_keys2, cudaFuncAttributeMaxDynamicSharedMemorySize, gk_smem);
  cudaFuncSetAttribute(lstm_step,  cudaFuncAttributeMaxDynamicSharedMemorySize, ls_smem);
  cudaFuncSetAttribute(att_step,   cudaFuncAttributeMaxDynamicSharedMemorySize, at_smem);

  prep_small<<<2048,256>>>(Wi,Wh,b,Wm,Wq,Wa,enc_h,enc_c);
  prep_big<<<32768,256>>>((const float4*)memory);
  gemm_keys2<<<dim3(4,2048),256,gk_smem>>>();
  for (int s=0;s<NSTEP;s++){
    lstm_step<<<dim3(16,8),256,ls_smem>>>(ids, s);
    att_step<<<256,256,at_smem>>>(out, v, Wf, bf, s);
  }
}